// round 1
// baseline (speedup 1.0000x reference)
#include <cuda_runtime.h>

#define DIM   1024
#define KC    32
#define TILE_D 256
#define NTILES (DIM / TILE_D)
#define TPB   128

// fma.rn.f32x2: packed dual-fp32 FMA (Blackwell). ptxas won't auto-fuse, must use PTX.
__device__ __forceinline__ unsigned long long fma2(unsigned long long a,
                                                   unsigned long long b,
                                                   unsigned long long c) {
    unsigned long long d;
    asm("fma.rn.f32x2 %0, %1, %2, %3;" : "=l"(d) : "l"(a), "l"(b), "l"(c));
    return d;
}

__global__ __launch_bounds__(TPB, 4)
void nkm_kernel(const float* __restrict__ X, const float* __restrict__ C,
                float* __restrict__ out, int N) {
    __shared__ float sC[KC * TILE_D];   // 32 KB centroid tile
    __shared__ float sSq[KC];           // running ||mu_j||^2

    const int tid = threadIdx.x;
    const int n  = blockIdx.x * TPB + tid;
    const int nc = (n < N) ? n : (N - 1);   // clamp so invalid threads read safely

    if (tid < KC) sSq[tid] = 0.0f;

    unsigned long long acc[KC];   // 32 accumulators, each a packed f32x2 (even/odd d lanes)
#pragma unroll
    for (int j = 0; j < KC; j++) acc[j] = 0ull;

    const float4* __restrict__ csrc = reinterpret_cast<const float4*>(C);

    for (int t = 0; t < NTILES; t++) {
        __syncthreads();  // protect smem reuse (and publishes sSq init on t==0)

        // ---- cooperative tile load: KC x TILE_D floats, vectorized ----
        float4* dst = reinterpret_cast<float4*>(sC);
#pragma unroll
        for (int i = tid; i < KC * TILE_D / 4; i += TPB) {
            int j  = i / (TILE_D / 4);
            int c4 = i % (TILE_D / 4);
            dst[i] = csrc[j * (DIM / 4) + t * (TILE_D / 4) + c4];
        }
        __syncthreads();

        // ---- sq partial: 4 threads per centroid row, 64 elems each ----
        {
            int j = tid >> 2, part = tid & 3;
            const float4* r = reinterpret_cast<const float4*>(sC + j * TILE_D + part * 64);
            float s = 0.0f;
#pragma unroll
            for (int i = 0; i < 16; i++) {
                float4 v = r[i];
                s += v.x * v.x + v.y * v.y + v.z * v.z + v.w * v.w;
            }
            s += __shfl_down_sync(0xffffffffu, s, 2);
            s += __shfl_down_sync(0xffffffffu, s, 1);
            if (part == 0) sSq[j] += s;   // unique writer per j; read only after final sync
        }

        // ---- main FMA loop over this D-tile ----
        const ulonglong2* __restrict__ cp =
            reinterpret_cast<const ulonglong2*>(sC);
        const ulonglong2* __restrict__ xp =
            reinterpret_cast<const ulonglong2*>(X + (size_t)nc * DIM + t * TILE_D);

        ulonglong2 xa = xp[0], xb = xp[1];   // 32 B of x (full sector)
#pragma unroll 1
        for (int d0 = 0; d0 < TILE_D; d0 += 8) {
            // prefetch next chunk (clamped: last iter redundantly reloads, harmless)
            int nxt = (d0 + 8 < TILE_D) ? (d0 + 8) : d0;
            ulonglong2 na = xp[nxt >> 2];
            ulonglong2 nb = xp[(nxt >> 2) + 1];

            int base = d0 >> 2;  // ulonglong2 index within tile row (row stride = TILE_D/4)
#pragma unroll
            for (int j = 0; j < KC; j++) {
                ulonglong2 ca = cp[j * (TILE_D / 4) + base];      // LDS.128 broadcast
                ulonglong2 cb = cp[j * (TILE_D / 4) + base + 1];
                acc[j] = fma2(xa.x, ca.x, acc[j]);
                acc[j] = fma2(xa.y, ca.y, acc[j]);
                acc[j] = fma2(xb.x, cb.x, acc[j]);
                acc[j] = fma2(xb.y, cb.y, acc[j]);
            }
            xa = na; xb = nb;
        }
    }
    __syncthreads();   // sSq fully accumulated & visible

    // ---- epilogue: s_j = 2*dot_j - ||mu_j||^2 ; out = top1(s) - top2(s) ----
    if (n < N) {
        float m1 = -__int_as_float(0x7f800000);  // -inf
        float m2 = m1;
#pragma unroll
        for (int j = 0; j < KC; j++) {
            float lo, hi;
            asm("mov.b64 {%0,%1}, %2;" : "=f"(lo), "=f"(hi) : "l"(acc[j]));
            float s = 2.0f * (lo + hi) - sSq[j];
            if (s > m1) { m2 = m1; m1 = s; }
            else if (s > m2) { m2 = s; }
        }
        out[n] = m1 - m2;
    }
}

extern "C" void kernel_launch(void* const* d_in, const int* in_sizes, int n_in,
                              void* d_out, int out_size) {
    const float* X = (const float*)d_in[0];       // [N, 1024]
    const float* C = (const float*)d_in[1];       // [32, 1024]
    float* out = (float*)d_out;                   // [N]
    int N = in_sizes[0] / DIM;
    int nb = (N + TPB - 1) / TPB;
    nkm_kernel<<<nb, TPB>>>(X, C, out, N);
}

// round 2
// speedup vs baseline: 1.3838x; 1.3838x over previous
#include <cuda_runtime.h>

#define DIM    1024
#define KC     32
#define TILE_D 256
#define PITCH  260              // floats; +4 pad so quad phases hit distinct banks
#define NTILES (DIM / TILE_D)
#define TPB    128

// fma.rn.f32x2: packed dual-fp32 FMA (Blackwell). ptxas never auto-fuses this.
__device__ __forceinline__ unsigned long long fma2(unsigned long long a,
                                                   unsigned long long b,
                                                   unsigned long long c) {
    unsigned long long d;
    asm("fma.rn.f32x2 %0, %1, %2, %3;" : "=l"(d) : "l"(a), "l"(b), "l"(c));
    return d;
}

__global__ __launch_bounds__(TPB, 3)
void nkm_kernel(const float* __restrict__ X, const float* __restrict__ C,
                float* __restrict__ out, int N) {
    __shared__ float sC[KC * PITCH];   // 33.3 KB centroid tile (pitched)
    __shared__ float sSq[KC];          // running ||mu_j||^2

    const int tid = threadIdx.x;
    const int q   = tid & 3;           // j phase: thread covers j ≡ q (mod 4)
    const int qd  = tid >> 2;          // row group 0..31
    const int rowBase = blockIdx.x * TPB + qd * 4;

    if (tid < KC) sSq[tid] = 0.0f;

    // acc[r][jj] : packed f32x2 dot-product accumulator for row r, j = q + 4*jj
    unsigned long long acc[4][8];
#pragma unroll
    for (int r = 0; r < 4; r++)
#pragma unroll
        for (int jj = 0; jj < 8; jj++) acc[r][jj] = 0ull;

    // row pointers (clamped; all 4 lanes of a quad read identical addresses)
    const ulonglong2* xr[4];
#pragma unroll
    for (int r = 0; r < 4; r++) {
        int rr = rowBase + r;
        if (rr >= N) rr = N - 1;
        xr[r] = reinterpret_cast<const ulonglong2*>(X + (size_t)rr * DIM);
    }

    const float4* __restrict__ csrc = reinterpret_cast<const float4*>(C);

    for (int t = 0; t < NTILES; t++) {
        __syncthreads();   // protect smem reuse (and publish sSq init at t==0)

        // ---- cooperative centroid tile load: 32 x 256 floats, pitched ----
#pragma unroll
        for (int i = tid; i < KC * TILE_D / 4; i += TPB) {
            int j  = i >> 6;       // / 64 float4 per row
            int c4 = i & 63;
            *reinterpret_cast<float4*>(sC + j * PITCH + c4 * 4) =
                csrc[j * (DIM / 4) + t * 64 + c4];
        }
        __syncthreads();

        // ---- sq partial: 4 threads per centroid row ----
        {
            int j = tid >> 2, part = tid & 3;
            const float4* rr = reinterpret_cast<const float4*>(sC + j * PITCH + part * 64);
            float s = 0.0f;
#pragma unroll
            for (int i = 0; i < 16; i++) {
                float4 v = rr[i];
                s += v.x * v.x + v.y * v.y + v.z * v.z + v.w * v.w;
            }
            s += __shfl_down_sync(0xffffffffu, s, 2);
            s += __shfl_down_sync(0xffffffffu, s, 1);
            if (part == 0) sSq[j] += s;   // unique writer; read after final sync
        }

        // ---- main loop: chunks of 4 d, x double-buffered ----
        const ulonglong2* __restrict__ cp = reinterpret_cast<const ulonglong2*>(sC);
        const int xoff = t * (TILE_D / 4);   // ulonglong2 offset into X row

        ulonglong2 xa[4];
#pragma unroll
        for (int r = 0; r < 4; r++) xa[r] = xr[r][xoff];

#pragma unroll 1
        for (int d0 = 0; d0 < TILE_D; d0 += 4) {
            int nxt = (d0 + 4 < TILE_D) ? (d0 + 4) : d0;   // last iter: harmless reload
            ulonglong2 na[4];
#pragma unroll
            for (int r = 0; r < 4; r++) na[r] = xr[r][xoff + (nxt >> 2)];

            const int base = d0 >> 2;
#pragma unroll
            for (int jj = 0; jj < 8; jj++) {
                int j = q + jj * 4;
                ulonglong2 ca = cp[j * (PITCH / 4) + base];   // LDS.128, conflict-free
#pragma unroll
                for (int r = 0; r < 4; r++) {
                    acc[r][jj] = fma2(xa[r].x, ca.x, acc[r][jj]);
                    acc[r][jj] = fma2(xa[r].y, ca.y, acc[r][jj]);
                }
            }
#pragma unroll
            for (int r = 0; r < 4; r++) xa[r] = na[r];
        }
    }
    __syncthreads();   // sSq fully accumulated & visible

    // ---- epilogue: s_j = 2*dot - ||mu_j||^2 ; per-row top2 ; quad merge ----
    float sq[8];
#pragma unroll
    for (int jj = 0; jj < 8; jj++) sq[jj] = sSq[q + jj * 4];

    const float NEG_INF = -__int_as_float(0x7f800000);
    float m1[4], m2[4];
#pragma unroll
    for (int r = 0; r < 4; r++) {
        m1[r] = NEG_INF;
        m2[r] = NEG_INF;
#pragma unroll
        for (int jj = 0; jj < 8; jj++) {
            float lo, hi;
            asm("mov.b64 {%0,%1}, %2;" : "=f"(lo), "=f"(hi) : "l"(acc[r][jj]));
            float s = 2.0f * (lo + hi) - sq[jj];
            if (s > m1[r]) { m2[r] = m1[r]; m1[r] = s; }
            else if (s > m2[r]) { m2[r] = s; }
        }
    }

    // merge top2 across the quad (lanes q=0..3 cover disjoint j sets)
#pragma unroll
    for (int delta = 1; delta <= 2; delta <<= 1) {
#pragma unroll
        for (int r = 0; r < 4; r++) {
            float om1 = __shfl_xor_sync(0xffffffffu, m1[r], delta);
            float om2 = __shfl_xor_sync(0xffffffffu, m2[r], delta);
            float nm1 = fmaxf(m1[r], om1);
            float nm2 = fmaxf(fminf(m1[r], om1), fmaxf(m2[r], om2));
            m1[r] = nm1;
            m2[r] = nm2;
        }
    }

    // lane q of each quad writes row rowBase + q
    int rowOut = rowBase + q;
    if (rowOut < N) out[rowOut] = m1[q] - m2[q];
}

extern "C" void kernel_launch(void* const* d_in, const int* in_sizes, int n_in,
                              void* d_out, int out_size) {
    const float* X = (const float*)d_in[0];   // [N, 1024]
    const float* C = (const float*)d_in[1];   // [32, 1024]
    float* out = (float*)d_out;               // [N]
    int N = in_sizes[0] / DIM;
    int nb = (N + TPB - 1) / TPB;
    nkm_kernel<<<nb, TPB>>>(X, C, out, N);
}

// round 3
// speedup vs baseline: 1.5003x; 1.0842x over previous
#include <cuda_runtime.h>

#define DIM     1024
#define KC      32
#define TILE_D  256
#define PITCH   260            // centroid row pitch (floats): +4 so q phases differ by 4 banks
#define NTILES  (DIM / TILE_D)
#define TPB     128
#define RPB     128            // rows per block
#define CHUNK_D 32
#define NCHUNK  (TILE_D / CHUNK_D)   // 8
#define XBLK    516            // floats per 4-d block of X tile: 128 rows * 4 + 4 pad
#define XBUF    (8 * XBLK)     // 4128 floats per chunk buffer

// fma.rn.f32x2: packed dual-fp32 FMA (Blackwell). ptxas never auto-fuses this.
__device__ __forceinline__ unsigned long long fma2(unsigned long long a,
                                                   unsigned long long b,
                                                   unsigned long long c) {
    unsigned long long d;
    asm("fma.rn.f32x2 %0, %1, %2, %3;" : "=l"(d) : "l"(a), "l"(b), "l"(c));
    return d;
}

__global__ __launch_bounds__(TPB, 3)
void nkm_kernel(const float* __restrict__ X, const float* __restrict__ C,
                float* __restrict__ out, int N) {
    extern __shared__ float smem[];
    float* sC  = smem;                  // KC*PITCH = 8320 floats
    float* sX  = smem + KC * PITCH;     // 2 * 4128 floats (double-buffered X chunk)
    float* sSq = sX + 2 * XBUF;         // 32 floats

    const int tid = threadIdx.x;
    const int q   = tid & 3;            // j phase: this thread covers j ≡ q (mod 4)
    const int qd  = tid >> 2;           // 0..31: row-group id (rows qd + 32r)
    const int w   = tid >> 5;
    const int l   = tid & 31;
    const int blockBase = blockIdx.x * RPB;

    if (tid < KC) sSq[tid] = 0.f;

    unsigned long long acc[4][8];       // [row r][jj], packed f32x2 over d-pairs
#pragma unroll
    for (int r = 0; r < 4; r++)
#pragma unroll
        for (int jj = 0; jj < 8; jj++) acc[r][jj] = 0ull;

    // ---- coalesced X loader setup ----
    // LDG #k: lane l reads row (w*32 + k*4 + (l>>3)), 16B piece (l&7) of the 128B chunk row
    const int pc   = l & 7;             // d piece within chunk (also smem d-block index)
    const int rsub = l >> 3;
    int xgbase[8];                      // float4 index into X per k (pc folded in)
#pragma unroll
    for (int k = 0; k < 8; k++) {
        int rg = blockBase + w * 32 + k * 4 + rsub;
        if (rg >= N) rg = N - 1;        // clamp: last block duplicates row N-1 (outputs guarded)
        xgbase[k] = rg * (DIM / 4) + pc;
    }
    const float4* __restrict__ X4 = reinterpret_cast<const float4*>(X);
    const int stsBase = pc * XBLK + (w * 32 + rsub) * 4;   // float index; + k*16 per k

    const float4* __restrict__ csrc = reinterpret_cast<const float4*>(C);
    float4 xreg[8];

    for (int t = 0; t < NTILES; t++) {
        __syncthreads();   // protect sC reuse (and publish sSq init at t==0)

        // ---- cooperative centroid tile load: 32 x 256 floats, pitched ----
#pragma unroll
        for (int i = tid; i < KC * TILE_D / 4; i += TPB) {
            int j  = i >> 6;
            int c4 = i & 63;
            *reinterpret_cast<float4*>(sC + j * PITCH + c4 * 4) =
                csrc[j * (DIM / 4) + t * 64 + c4];
        }
        __syncthreads();

        // ---- sq partial: 4 threads per centroid row ----
        {
            int j = tid >> 2, part = tid & 3;
            const float4* rr = reinterpret_cast<const float4*>(sC + j * PITCH + part * 64);
            float s = 0.0f;
#pragma unroll
            for (int i = 0; i < 16; i++) {
                float4 v = rr[i];
                s += v.x * v.x + v.y * v.y + v.z * v.z + v.w * v.w;
            }
            s += __shfl_down_sync(0xffffffffu, s, 2);
            s += __shfl_down_sync(0xffffffffu, s, 1);
            if (part == 0) sSq[j] += s;   // unique writer; read after final sync
        }

        // ---- X chunk pipeline over this tile ----
        const int tile_d4 = t * (TILE_D / 4);   // float4 column offset of tile

        // prologue: chunk 0 -> buf0
#pragma unroll
        for (int k = 0; k < 8; k++) xreg[k] = X4[xgbase[k] + tile_d4];
#pragma unroll
        for (int k = 0; k < 8; k++)
            *reinterpret_cast<float4*>(sX + stsBase + k * 16) = xreg[k];
        __syncthreads();

#pragma unroll 1
        for (int c = 0; c < NCHUNK; c++) {
            // prefetch next chunk into registers (LDG latency hidden by FMAs below)
            if (c + 1 < NCHUNK) {
                const int off = tile_d4 + (c + 1) * 8;
#pragma unroll
                for (int k = 0; k < 8; k++) xreg[k] = X4[xgbase[k] + off];
            }

            // compute chunk c from buf[c&1]
            const float* xb = sX + (c & 1) * XBUF;
            const ulonglong2* __restrict__ cp = reinterpret_cast<const ulonglong2*>(sC);
#pragma unroll
            for (int b = 0; b < 8; b++) {
                ulonglong2 xa[4];
#pragma unroll
                for (int r = 0; r < 4; r++)
                    xa[r] = *reinterpret_cast<const ulonglong2*>(
                        xb + b * XBLK + qd * 4 + r * 128);
                const int cidx = c * 8 + b;   // float4 column within tile
#pragma unroll
                for (int jj = 0; jj < 8; jj++) {
                    ulonglong2 ca = cp[(q + 4 * jj) * (PITCH / 4) + cidx];
#pragma unroll
                    for (int r = 0; r < 4; r++) {
                        acc[r][jj] = fma2(xa[r].x, ca.x, acc[r][jj]);
                        acc[r][jj] = fma2(xa[r].y, ca.y, acc[r][jj]);
                    }
                }
            }

            // store prefetched chunk into the other buffer (last read ended iter c-1)
            if (c + 1 < NCHUNK) {
                float* xw = sX + ((c + 1) & 1) * XBUF;
#pragma unroll
                for (int k = 0; k < 8; k++)
                    *reinterpret_cast<float4*>(xw + stsBase + k * 16) = xreg[k];
            }
            __syncthreads();
        }
    }

    // ---- epilogue: s_j = 2*dot - ||mu_j||^2 ; per-row top2 ; quad merge ----
    float sq[8];
#pragma unroll
    for (int jj = 0; jj < 8; jj++) sq[jj] = sSq[q + jj * 4];

    const float NEG_INF = -__int_as_float(0x7f800000);
    float m1[4], m2[4];
#pragma unroll
    for (int r = 0; r < 4; r++) {
        m1[r] = NEG_INF;
        m2[r] = NEG_INF;
#pragma unroll
        for (int jj = 0; jj < 8; jj++) {
            float lo, hi;
            asm("mov.b64 {%0,%1}, %2;" : "=f"(lo), "=f"(hi) : "l"(acc[r][jj]));
            float s = 2.0f * (lo + hi) - sq[jj];
            if (s > m1[r]) { m2[r] = m1[r]; m1[r] = s; }
            else if (s > m2[r]) { m2[r] = s; }
        }
    }

    // merge top2 across the quad (lanes q=0..3 cover disjoint j sets)
#pragma unroll
    for (int delta = 1; delta <= 2; delta <<= 1) {
#pragma unroll
        for (int r = 0; r < 4; r++) {
            float om1 = __shfl_xor_sync(0xffffffffu, m1[r], delta);
            float om2 = __shfl_xor_sync(0xffffffffu, m2[r], delta);
            float nm1 = fmaxf(m1[r], om1);
            float nm2 = fmaxf(fminf(m1[r], om1), fmaxf(m2[r], om2));
            m1[r] = nm1;
            m2[r] = nm2;
        }
    }

    // lane q writes its r=q row: rows are qd + 32r
    int rowOut = blockBase + qd + 32 * q;
    if (rowOut < N) out[rowOut] = m1[q] - m2[q];
}

extern "C" void kernel_launch(void* const* d_in, const int* in_sizes, int n_in,
                              void* d_out, int out_size) {
    const float* X = (const float*)d_in[0];   // [N, 1024]
    const float* C = (const float*)d_in[1];   // [32, 1024]
    float* out = (float*)d_out;               // [N]
    int N = in_sizes[0] / DIM;
    int nb = (N + RPB - 1) / RPB;

    const int smemBytes = (KC * PITCH + 2 * XBUF + KC) * 4;   // 66432 B
    cudaFuncSetAttribute(nkm_kernel, cudaFuncAttributeMaxDynamicSharedMemorySize,
                         smemBytes);
    nkm_kernel<<<nb, TPB, smemBytes>>>(X, C, out, N);
}

// round 6
// speedup vs baseline: 2.3936x; 1.5954x over previous
#include <cuda_runtime.h>
#include <cstdint>

#define DIM    1024
#define KC     32
#define MROWS  64
#define TPB    128
#define KCH    32
#define NCH    (DIM / KCH)       // 32 chunks
#define PITCHW 20                // 32-bit words per row (16 data + 4 pad)
#define XH_OFF 0
#define XL_OFF (MROWS * PITCHW)          // 1280
#define CH_OFF (2 * MROWS * PITCHW)      // 2560
#define CL_OFF (CH_OFF + KC * PITCHW)    // 3200
#define STAGE_W (CL_OFF + KC * PITCHW)   // 3840 words = 15360 B

// split fp32 pair into bf16x2 hi + bf16x2 lo (RN both stages); low half = first arg
static __device__ __forceinline__ void split2(float x0, float x1,
                                              uint32_t& hi2, uint32_t& lo2) {
    asm("cvt.rn.bf16x2.f32 %0, %1, %2;" : "=r"(hi2) : "f"(x1), "f"(x0));
    float h0 = __uint_as_float(hi2 << 16);
    float h1 = __uint_as_float(hi2 & 0xFFFF0000u);
    float l0 = x0 - h0, l1 = x1 - h1;
    asm("cvt.rn.bf16x2.f32 %0, %1, %2;" : "=r"(lo2) : "f"(l1), "f"(l0));
}

static __device__ __forceinline__ void mma_bf16(float* c, const uint32_t* a,
                                                uint32_t b0, uint32_t b1) {
    asm volatile(
        "mma.sync.aligned.m16n8k16.row.col.f32.bf16.bf16.f32 "
        "{%0,%1,%2,%3}, {%4,%5,%6,%7}, {%8,%9}, {%0,%1,%2,%3};"
        : "+f"(c[0]), "+f"(c[1]), "+f"(c[2]), "+f"(c[3])
        : "r"(a[0]), "r"(a[1]), "r"(a[2]), "r"(a[3]), "r"(b0), "r"(b1));
}

__global__ __launch_bounds__(TPB, 4)
void nkm_mma(const float* __restrict__ X, const float* __restrict__ C,
             float* __restrict__ out, int N) {
    __shared__ uint32_t sbuf[2][STAGE_W];   // 30720 B double-buffered stage
    __shared__ float sSq[KC];

    const int tid  = threadIdx.x;
    const int w    = tid >> 5;
    const int lane = tid & 31;
    const int g    = lane >> 2;      // fragment row group 0..7
    const int ql   = lane & 3;       // fragment k/col phase 0..3
    const int blockBase = blockIdx.x * MROWS;

    const float4* __restrict__ X4 = reinterpret_cast<const float4*>(X);
    const float4* __restrict__ C4 = reinterpret_cast<const float4*>(C);

    // ---- loader constants ----
    // X tile: 64 rows x 8 float4; thread loads rows (tid>>3)+16j, col4 = tid&7
    int xg[4];
    uint32_t stsX[4];
#pragma unroll
    for (int j = 0; j < 4; j++) {
        int row = (tid >> 3) + 16 * j;
        int gr  = blockBase + row;
        if (gr >= N) gr = N - 1;            // clamp; outputs guarded
        xg[j]   = gr * (DIM / 4) + (tid & 7);
        stsX[j] = (uint32_t)(row * PITCHW + (tid & 7) * 2);
    }
    // C tile: 32 rows x 8 float4; thread loads rows (tid>>3)+16j (j=0,1)
    int cgi[2];
    uint32_t stsC[2];
#pragma unroll
    for (int j = 0; j < 2; j++) {
        int row = (tid >> 3) + 16 * j;
        cgi[j]  = row * (DIM / 4) + (tid & 7);
        stsC[j] = (uint32_t)(row * PITCHW + (tid & 7) * 2);
    }

    float acc[4][4];                 // [ntile][c-frag], rows {g, g+8}, cols per nt
#pragma unroll
    for (int nt = 0; nt < 4; nt++)
#pragma unroll
        for (int i = 0; i < 4; i++) acc[nt][i] = 0.0f;

    float sq0 = 0.0f, sq1 = 0.0f;    // ||mu||^2 partials for rows tid>>3, +16

    // fragment LDS bases (word indices)
    const int abase = (16 * w + g) * PITCHW + ql;

    // ---- prologue: chunk 0 -> buf 0 ----
    {
        float4 xr[4], cr[2];
#pragma unroll
        for (int j = 0; j < 4; j++) xr[j] = X4[xg[j]];
#pragma unroll
        for (int j = 0; j < 2; j++) cr[j] = C4[cgi[j]];
        sq0 += cr[0].x * cr[0].x + cr[0].y * cr[0].y + cr[0].z * cr[0].z + cr[0].w * cr[0].w;
        sq1 += cr[1].x * cr[1].x + cr[1].y * cr[1].y + cr[1].z * cr[1].z + cr[1].w * cr[1].w;
        uint32_t* b = sbuf[0];
#pragma unroll
        for (int j = 0; j < 4; j++) {
            uint32_t h0, l0, h1, l1;
            split2(xr[j].x, xr[j].y, h0, l0);
            split2(xr[j].z, xr[j].w, h1, l1);
            *reinterpret_cast<uint2*>(b + XH_OFF + stsX[j]) = make_uint2(h0, h1);
            *reinterpret_cast<uint2*>(b + XL_OFF + stsX[j]) = make_uint2(l0, l1);
        }
#pragma unroll
        for (int j = 0; j < 2; j++) {
            uint32_t h0, l0, h1, l1;
            split2(cr[j].x, cr[j].y, h0, l0);
            split2(cr[j].z, cr[j].w, h1, l1);
            *reinterpret_cast<uint2*>(b + CH_OFF + stsC[j]) = make_uint2(h0, h1);
            *reinterpret_cast<uint2*>(b + CL_OFF + stsC[j]) = make_uint2(l0, l1);
        }
    }
    __syncthreads();

    // ---- main loop ----
#pragma unroll 1
    for (int kt = 0; kt < NCH; kt++) {
        float4 xr[4], cr[2];
        const bool more = (kt + 1 < NCH);
        if (more) {
            const int kc4 = (kt + 1) * 8;
#pragma unroll
            for (int j = 0; j < 4; j++) xr[j] = X4[xg[j] + kc4];
#pragma unroll
            for (int j = 0; j < 2; j++) cr[j] = C4[cgi[j] + kc4];
            sq0 += cr[0].x * cr[0].x + cr[0].y * cr[0].y + cr[0].z * cr[0].z + cr[0].w * cr[0].w;
            sq1 += cr[1].x * cr[1].x + cr[1].y * cr[1].y + cr[1].z * cr[1].z + cr[1].w * cr[1].w;
        }

        // compute chunk kt from sbuf[kt&1]
        const uint32_t* bp = sbuf[kt & 1];
#pragma unroll
        for (int ks = 0; ks < 2; ks++) {
            const int ko = 8 * ks;
            uint32_t ah[4], al[4];
            const int a0 = XH_OFF + abase + ko;
            ah[0] = bp[a0];
            ah[1] = bp[a0 + 8 * PITCHW];
            ah[2] = bp[a0 + 4];
            ah[3] = bp[a0 + 8 * PITCHW + 4];
            const int a0l = a0 + (XL_OFF - XH_OFF);
            al[0] = bp[a0l];
            al[1] = bp[a0l + 8 * PITCHW];
            al[2] = bp[a0l + 4];
            al[3] = bp[a0l + 8 * PITCHW + 4];
#pragma unroll
            for (int nt = 0; nt < 4; nt++) {
                const int b0i = CH_OFF + (8 * nt + g) * PITCHW + ql + ko;
                uint32_t bh0 = bp[b0i], bh1 = bp[b0i + 4];
                uint32_t bl0 = bp[b0i + (CL_OFF - CH_OFF)];
                uint32_t bl1 = bp[b0i + (CL_OFF - CH_OFF) + 4];
                mma_bf16(acc[nt], ah, bh0, bh1);   // hi*hi
                mma_bf16(acc[nt], ah, bl0, bl1);   // hi*lo
                mma_bf16(acc[nt], al, bh0, bh1);   // lo*hi
            }
        }

        if (more) {
            uint32_t* b = sbuf[(kt + 1) & 1];
#pragma unroll
            for (int j = 0; j < 4; j++) {
                uint32_t h0, l0, h1, l1;
                split2(xr[j].x, xr[j].y, h0, l0);
                split2(xr[j].z, xr[j].w, h1, l1);
                *reinterpret_cast<uint2*>(b + XH_OFF + stsX[j]) = make_uint2(h0, h1);
                *reinterpret_cast<uint2*>(b + XL_OFF + stsX[j]) = make_uint2(l0, l1);
            }
#pragma unroll
            for (int j = 0; j < 2; j++) {
                uint32_t h0, l0, h1, l1;
                split2(cr[j].x, cr[j].y, h0, l0);
                split2(cr[j].z, cr[j].w, h1, l1);
                *reinterpret_cast<uint2*>(b + CH_OFF + stsC[j]) = make_uint2(h0, h1);
                *reinterpret_cast<uint2*>(b + CL_OFF + stsC[j]) = make_uint2(l0, l1);
            }
        }
        __syncthreads();
    }

    // ---- ||mu||^2 reduce: 8 threads per class row ----
    sq0 += __shfl_down_sync(0xffffffffu, sq0, 4, 8);
    sq0 += __shfl_down_sync(0xffffffffu, sq0, 2, 8);
    sq0 += __shfl_down_sync(0xffffffffu, sq0, 1, 8);
    sq1 += __shfl_down_sync(0xffffffffu, sq1, 4, 8);
    sq1 += __shfl_down_sync(0xffffffffu, sq1, 2, 8);
    sq1 += __shfl_down_sync(0xffffffffu, sq1, 1, 8);
    if ((tid & 7) == 0) {
        sSq[tid >> 3]        = sq0;
        sSq[(tid >> 3) + 16] = sq1;
    }
    __syncthreads();

    // ---- epilogue: s = 2*dot - sq ; top2 per row; merge across 4 lanes ----
    const float NEG_INF = -__int_as_float(0x7f800000);
    float m1[2] = {NEG_INF, NEG_INF};
    float m2[2] = {NEG_INF, NEG_INF};
#pragma unroll
    for (int nt = 0; nt < 4; nt++) {
        const int c0 = 8 * nt + ql * 2;
        const float q0 = sSq[c0], q1 = sSq[c0 + 1];
        // row g: acc[nt][0], acc[nt][1]; row g+8: acc[nt][2], acc[nt][3]
        float s;
        s = 2.0f * acc[nt][0] - q0;
        if (s > m1[0]) { m2[0] = m1[0]; m1[0] = s; } else if (s > m2[0]) m2[0] = s;
        s = 2.0f * acc[nt][1] - q1;
        if (s > m1[0]) { m2[0] = m1[0]; m1[0] = s; } else if (s > m2[0]) m2[0] = s;
        s = 2.0f * acc[nt][2] - q0;
        if (s > m1[1]) { m2[1] = m1[1]; m1[1] = s; } else if (s > m2[1]) m2[1] = s;
        s = 2.0f * acc[nt][3] - q1;
        if (s > m1[1]) { m2[1] = m1[1]; m1[1] = s; } else if (s > m2[1]) m2[1] = s;
    }
#pragma unroll
    for (int delta = 1; delta <= 2; delta <<= 1) {
#pragma unroll
        for (int r = 0; r < 2; r++) {
            float om1 = __shfl_xor_sync(0xffffffffu, m1[r], delta);
            float om2 = __shfl_xor_sync(0xffffffffu, m2[r], delta);
            float nm1 = fmaxf(m1[r], om1);
            float nm2 = fmaxf(fminf(m1[r], om1), fmaxf(m2[r], om2));
            m1[r] = nm1;
            m2[r] = nm2;
        }
    }
    if (ql == 0) {
        int r0 = blockBase + 16 * w + g;
        if (r0 < N)     out[r0]     = m1[0] - m2[0];
        if (r0 + 8 < N) out[r0 + 8] = m1[1] - m2[1];
    }
}

extern "C" void kernel_launch(void* const* d_in, const int* in_sizes, int n_in,
                              void* d_out, int out_size) {
    const float* X = (const float*)d_in[0];   // [N, 1024]
    const float* C = (const float*)d_in[1];   // [32, 1024]
    float* out = (float*)d_out;               // [N]
    int N = in_sizes[0] / DIM;
    int nb = (N + MROWS - 1) / MROWS;
    nkm_mma<<<nb, TPB>>>(X, C, out, N);
}